// round 8
// baseline (speedup 1.0000x reference)
#include <cuda_runtime.h>
#include <cstdint>

#define BB 2
#define SS 4096
#define DD 128
#define HALF 64
#define TM 64            // rows per CTA (both kernels)
#define KU 192           // key union per tile
#define NT 512           // 16 warps

// Q/K/V scratch as tf32 bit patterns (Q pre-scaled by 1/sqrt(D))
__device__ uint32_t g_q[BB * SS * DD];
__device__ uint32_t g_k[BB * SS * DD];
__device__ uint32_t g_v[BB * SS * DD];

__device__ __forceinline__ uint32_t f2tf32(float f) {
    uint32_t u;
    asm("cvt.rna.tf32.f32 %0, %1;" : "=r"(u) : "f"(f));
    return u;
}
__device__ __forceinline__ uint32_t smem_u32(const void* p) {
    uint32_t a;
    asm("{ .reg .u64 t; cvta.to.shared.u64 t, %1; cvt.u32.u64 %0, t; }" : "=r"(a) : "l"(p));
    return a;
}
// 16B async copy, src_size<16 zero-fills
__device__ __forceinline__ void cpa(uint32_t dst, const void* src, int srcsz) {
    asm volatile("cp.async.cg.shared.global [%0], [%1], 16, %2;"
                 :: "r"(dst), "l"(src), "r"(srcsz) : "memory");
}
#define CP_COMMIT() asm volatile("cp.async.commit_group;" ::: "memory")
#define CP_WAIT(n)  asm volatile("cp.async.wait_group %0;" :: "n"(n) : "memory")

// D += A*B  (m16n8k8, tf32, row.col)
__device__ __forceinline__ void mma8(float* c, const uint32_t* a, uint32_t b0, uint32_t b1) {
    asm volatile(
        "mma.sync.aligned.m16n8k8.row.col.f32.tf32.tf32.f32 "
        "{%0,%1,%2,%3}, {%4,%5,%6,%7}, {%8,%9}, {%0,%1,%2,%3};"
        : "+f"(c[0]), "+f"(c[1]), "+f"(c[2]), "+f"(c[3])
        : "r"(a[0]), "r"(a[1]), "r"(a[2]), "r"(a[3]), "r"(b0), "r"(b1));
}

// smem pitches (words): A-pattern pitch%32==4 (132,196), B-pattern pitch%32==8 (136)
// all pitches * 4 are 16B-aligned (132*4=528, 136*4=544, 196*4=784)
#define XP 132
#define WP 136
#define PP 196

// in-place fp32 -> tf32-bits conversion of a smem region laid out with pitch P,
// nrows rows x 128 data cols (vectorized float4)
__device__ __forceinline__ void cvt_region(uint32_t* s, int pitch, int nrows, int tid) {
    for (int i = tid; i < nrows * 32; i += NT) {
        int r = i >> 5, c4 = (i & 31) << 2;
        float4 v = *(const float4*)&s[r * pitch + c4];
        uint4 u;
        u.x = f2tf32(v.x); u.y = f2tf32(v.y); u.z = f2tf32(v.z); u.w = f2tf32(v.w);
        *(uint4*)&s[r * pitch + c4] = u;
    }
}

// ---------------------------------------------------------------------------
// Kernel 1: QKV projection, W double-buffered via cp.async. grid=128, 512 thr.
// warp tile: m16 x n32 (wr = w&3 rows, wc = w>>2 cols)
// ---------------------------------------------------------------------------
#define QXS_W (TM * XP)       // 8448
#define QWS_W (DD * WP)       // 17408
#define QKV_SMEM ((QXS_W + 2 * QWS_W) * 4)   // 173056

__global__ __launch_bounds__(NT, 1) void qkv_kernel(
    const float* __restrict__ x,
    const float* __restrict__ Wq, const float* __restrict__ bq,
    const float* __restrict__ Wk, const float* __restrict__ bk,
    const float* __restrict__ Wv, const float* __restrict__ bv)
{
    extern __shared__ uint32_t smem[];
    uint32_t* Xs  = smem;               // [64][XP]  fp32 -> tf32 bits
    uint32_t* WsA = smem + QXS_W;       // [128][WP]
    uint32_t* WsB = WsA + QWS_W;

    const uint32_t sb   = smem_u32(smem);
    const uint32_t xs_b = sb;
    const uint32_t wsA  = sb + QXS_W * 4;
    const uint32_t wsB  = wsA + QWS_W * 4;

    const int tid = threadIdx.x, w = tid >> 5, lane = tid & 31;
    const int gy = lane >> 2, gx = lane & 3;
    const int m0 = blockIdx.x * TM;
    const int r0 = 16 * (w & 3);
    const int c0 = 32 * (w >> 2);

    // group0: X + Wq ; group1: Wk
    for (int i = tid; i < TM * 32; i += NT) {
        int m = i >> 5, c = (i & 31) << 2;
        cpa(xs_b + (uint32_t)(m * XP + c) * 4, &x[(m0 + m) * DD + c], 16);
    }
    for (int i = tid; i < DD * 32; i += NT) {
        int d = i >> 5, c = (i & 31) << 2;
        cpa(wsA + (uint32_t)(d * WP + c) * 4, &Wq[d * DD + c], 16);
    }
    CP_COMMIT();
    for (int i = tid; i < DD * 32; i += NT) {
        int d = i >> 5, c = (i & 31) << 2;
        cpa(wsB + (uint32_t)(d * WP + c) * 4, &Wk[d * DD + c], 16);
    }
    CP_COMMIT();
    CP_WAIT(1);
    __syncthreads();
    cvt_region(Xs, XP, TM, tid);
    cvt_region(WsA, WP, DD, tid);
    __syncthreads();

    const float scale = 0.088388347648318447f;  // 1/sqrt(128)

    auto run_mma = [&](const uint32_t* Wf, float acc[4][4]) {
        #pragma unroll
        for (int t = 0; t < 4; t++)
            #pragma unroll
            for (int c = 0; c < 4; c++) acc[t][c] = 0.f;
        #pragma unroll
        for (int ks = 0; ks < 16; ks++) {
            const int k0 = 8 * ks;
            uint32_t a[4];
            a[0] = Xs[(r0 + gy) * XP + k0 + gx];
            a[1] = Xs[(r0 + gy + 8) * XP + k0 + gx];
            a[2] = Xs[(r0 + gy) * XP + k0 + gx + 4];
            a[3] = Xs[(r0 + gy + 8) * XP + k0 + gx + 4];
            #pragma unroll
            for (int t = 0; t < 4; t++) {
                int n0 = c0 + 8 * t;
                uint32_t b0 = Wf[(k0 + gx) * WP + n0 + gy];
                uint32_t b1 = Wf[(k0 + gx + 4) * WP + n0 + gy];
                mma8(acc[t], a, b0, b1);
            }
        }
    };
    auto store_r = [&](uint32_t* dst, const float* bias, float scl, float acc[4][4]) {
        #pragma unroll
        for (int t = 0; t < 4; t++) {
            int col = c0 + 8 * t + 2 * gx;
            float bx = bias[col], by = bias[col + 1];
            uint2 v0 = make_uint2(f2tf32((acc[t][0] + bx) * scl), f2tf32((acc[t][1] + by) * scl));
            uint2 v1 = make_uint2(f2tf32((acc[t][2] + bx) * scl), f2tf32((acc[t][3] + by) * scl));
            *(uint2*)&dst[(size_t)(m0 + r0 + gy) * DD + col]     = v0;
            *(uint2*)&dst[(size_t)(m0 + r0 + gy + 8) * DD + col] = v1;
        }
    };

    float acc[4][4];
    run_mma(WsA, acc);               // Q (Wk streaming in behind)
    store_r(g_q, bq, scale, acc);

    CP_WAIT(0);                      // Wk landed
    __syncthreads();                 // all warps done reading WsA
    for (int i = tid; i < DD * 32; i += NT) {
        int d = i >> 5, c = (i & 31) << 2;
        cpa(wsA + (uint32_t)(d * WP + c) * 4, &Wv[d * DD + c], 16);
    }
    CP_COMMIT();
    cvt_region(WsB, WP, DD, tid);
    __syncthreads();

    run_mma(WsB, acc);               // K (Wv streaming in behind)
    store_r(g_k, bk, 1.f, acc);

    CP_WAIT(0);
    __syncthreads();
    cvt_region(WsA, WP, DD, tid);
    __syncthreads();

    run_mma(WsA, acc);               // V
    store_r(g_v, bv, 1.f, acc);
}

// ---------------------------------------------------------------------------
// Kernel 2: sliding-window attention. grid=128, 512 threads (16 warps).
// MMA1 warp tile m16 x n48; MMA2 warp tile m16 x n32.
// ---------------------------------------------------------------------------
#define AQS_W (TM * XP)       // 8448
#define AKV_W (KU * WP)       // 26112 (K at pitch XP, then V at pitch WP)
#define APS_W (TM * PP)       // 12544
#define ATTN_SMEM ((AQS_W + AKV_W + APS_W) * 4)   // 188416

__global__ __launch_bounds__(NT, 1) void attn_kernel(float* __restrict__ out)
{
    extern __shared__ uint32_t smem[];
    const uint32_t* Qs = smem;                    // [64][XP] tf32 bits
    const uint32_t* KV = smem + AQS_W;            // K:[192][XP] / V:[192][WP]
    float*          Ps = (float*)(smem + AQS_W + AKV_W);  // [64][PP]

    const uint32_t sb   = smem_u32(smem);
    const uint32_t qs_b = sb;
    const uint32_t kv_b = sb + AQS_W * 4;

    const int tid = threadIdx.x, w = tid >> 5, lane = tid & 31;
    const int gy = lane >> 2, gx = lane & 3;
    const int b  = blockIdx.x >> 6;
    const int q0 = (blockIdx.x & 63) * TM;
    const int kb = q0 - HALF;

    const uint32_t* qg = g_q + (size_t)b * SS * DD;
    const uint32_t* kg = g_k + (size_t)b * SS * DD;
    const uint32_t* vg = g_v + (size_t)b * SS * DD;

    // stage Q + K (zero-fill OOB rows)
    for (int i = tid; i < TM * 32; i += NT) {
        int m = i >> 5, c = (i & 31) << 2;
        cpa(qs_b + (uint32_t)(m * XP + c) * 4, &qg[(q0 + m) * DD + c], 16);
    }
    for (int i = tid; i < KU * 32; i += NT) {
        int j = i >> 5, c = (i & 31) << 2;
        int key = kb + j;
        int ok = (key >= 0 && key < SS);
        cpa(kv_b + (uint32_t)(j * XP + c) * 4, &kg[(size_t)(ok ? key : 0) * DD + c], ok ? 16 : 0);
    }
    CP_COMMIT();
    CP_WAIT(0);
    __syncthreads();

    // ---- S = Q @ K^T : warp = m16 x n48 (6 tiles) ----
    const int r0 = 16 * (w & 3);
    const int cb = 48 * (w >> 2);
    {
        float sacc[6][4];
        #pragma unroll
        for (int t = 0; t < 6; t++)
            #pragma unroll
            for (int c = 0; c < 4; c++) sacc[t][c] = 0.f;

        #pragma unroll
        for (int ks = 0; ks < 16; ks++) {
            const int k0 = 8 * ks;
            uint32_t a[4];
            a[0] = Qs[(r0 + gy) * XP + k0 + gx];
            a[1] = Qs[(r0 + gy + 8) * XP + k0 + gx];
            a[2] = Qs[(r0 + gy) * XP + k0 + gx + 4];
            a[3] = Qs[(r0 + gy + 8) * XP + k0 + gx + 4];
            #pragma unroll
            for (int t = 0; t < 6; t++) {
                int n0 = cb + 8 * t;
                uint32_t b0 = KV[(n0 + gy) * XP + k0 + gx];
                uint32_t b1 = KV[(n0 + gy) * XP + k0 + gx + 4];
                mma8(sacc[t], a, b0, b1);
            }
        }

        #pragma unroll
        for (int t = 0; t < 6; t++) {
            #pragma unroll
            for (int h = 0; h < 2; h++) {
                int q = r0 + gy + 8 * h;
                #pragma unroll
                for (int cc = 0; cc < 2; cc++) {
                    int j   = cb + 8 * t + 2 * gx + cc;
                    int key = kb + j;
                    int dj  = j - q;
                    bool valid = (dj >= 0) && (dj <= 2 * HALF) && (key >= 0) && (key < SS);
                    Ps[q * PP + j] = valid ? sacc[t][2 * h + cc] : -1e30f;
                }
            }
        }
    }
    __syncthreads();          // all MMA1 reads of KV done; Ps complete

    // ---- fire V copy (overlaps the whole softmax) ----
    for (int i = tid; i < KU * 32; i += NT) {
        int j = i >> 5, c = (i & 31) << 2;
        int key = kb + j;
        int ok = (key >= 0 && key < SS);
        cpa(kv_b + (uint32_t)(j * WP + c) * 4, &vg[(size_t)(ok ? key : 0) * DD + c], ok ? 16 : 0);
    }
    CP_COMMIT();

    // ---- softmax: 8 threads per row; final pass stores tf32 bits ----
    {
        int row = tid >> 3, sub = tid & 7;
        float m = -1e30f;
        for (int j = sub; j < KU; j += 8) m = fmaxf(m, Ps[row * PP + j]);
        m = fmaxf(m, __shfl_xor_sync(0xffffffffu, m, 1));
        m = fmaxf(m, __shfl_xor_sync(0xffffffffu, m, 2));
        m = fmaxf(m, __shfl_xor_sync(0xffffffffu, m, 4));
        float sum = 0.f;
        for (int j = sub; j < KU; j += 8) {
            float s = Ps[row * PP + j];
            float p = (s < -1e29f) ? 0.f : __expf(s - m);
            Ps[row * PP + j] = p;
            sum += p;
        }
        sum += __shfl_xor_sync(0xffffffffu, sum, 1);
        sum += __shfl_xor_sync(0xffffffffu, sum, 2);
        sum += __shfl_xor_sync(0xffffffffu, sum, 4);
        float inv = 1.f / sum;
        for (int j = sub; j < KU; j += 8)
            ((uint32_t*)Ps)[row * PP + j] = f2tf32(Ps[row * PP + j] * inv);
    }
    CP_WAIT(0);
    __syncthreads();

    // ---- O = P @ V : warp = m16 x n32 (4 tiles), 24 k-steps ----
    {
        const int d0 = 32 * (w >> 2);
        float oacc[4][4];
        #pragma unroll
        for (int t = 0; t < 4; t++)
            #pragma unroll
            for (int c = 0; c < 4; c++) oacc[t][c] = 0.f;

        const uint32_t* Pu = (const uint32_t*)Ps;
        #pragma unroll
        for (int ks = 0; ks < 24; ks++) {
            const int k0 = 8 * ks;
            uint32_t a[4];
            a[0] = Pu[(r0 + gy) * PP + k0 + gx];
            a[1] = Pu[(r0 + gy + 8) * PP + k0 + gx];
            a[2] = Pu[(r0 + gy) * PP + k0 + gx + 4];
            a[3] = Pu[(r0 + gy + 8) * PP + k0 + gx + 4];
            #pragma unroll
            for (int t = 0; t < 4; t++) {
                int n0 = d0 + 8 * t;
                uint32_t b0 = KV[(k0 + gx) * WP + n0 + gy];
                uint32_t b1 = KV[(k0 + gx + 4) * WP + n0 + gy];
                mma8(oacc[t], a, b0, b1);
            }
        }

        float* ob = out + (size_t)(b * SS + q0) * DD;
        #pragma unroll
        for (int t = 0; t < 4; t++) {
            int col = d0 + 8 * t + 2 * gx;
            *(float2*)&ob[(r0 + gy) * DD + col]     = make_float2(oacc[t][0], oacc[t][1]);
            *(float2*)&ob[(r0 + gy + 8) * DD + col] = make_float2(oacc[t][2], oacc[t][3]);
        }
    }
}

// ---------------------------------------------------------------------------
extern "C" void kernel_launch(void* const* d_in, const int* in_sizes, int n_in,
                              void* d_out, int out_size)
{
    const float* x  = (const float*)d_in[0];
    const float* Wq = (const float*)d_in[1];
    const float* bq = (const float*)d_in[2];
    const float* Wk = (const float*)d_in[3];
    const float* bk = (const float*)d_in[4];
    const float* Wv = (const float*)d_in[5];
    const float* bv = (const float*)d_in[6];
    float* out = (float*)d_out;

    cudaFuncSetAttribute(qkv_kernel,  cudaFuncAttributeMaxDynamicSharedMemorySize, QKV_SMEM);
    cudaFuncSetAttribute(attn_kernel, cudaFuncAttributeMaxDynamicSharedMemorySize, ATTN_SMEM);

    qkv_kernel<<<(BB * SS) / TM, NT, QKV_SMEM>>>(x, Wq, bq, Wk, bk, Wv, bv);
    attn_kernel<<<BB * (SS / TM), NT, ATTN_SMEM>>>(out);
}